// round 1
// baseline (speedup 1.0000x reference)
#include <cuda_runtime.h>
#include <cuda_bf16.h>
#include <math.h>

// ---------------------------------------------------------------------------
// DeepOHeat_ST: 4 trunk MLPs + branch MLP -> rank-64 CP outer product.
//
// Stage 1 (mlp_kernel): compute trunk outputs t[d][z][n] (z-major for
//   coalesced GEMM-side reads) and branch outputs br[z][b].
// Stage 2 (cp_kernel): out[b,i,j,k,l] = sum_z (t1[i,z]*t2[j,z]) *
//   (br[b,z]*t3[k,z]*t4[l,z])  == 4096x16384x64 fp32 GEMM with on-the-fly
//   operand construction in shared memory.
// ---------------------------------------------------------------------------

#define H 256
#define R 64
#define NF 64

// scratch: trunk outputs, stored [trunk][z][n]  (trunk 3 only n<32 valid)
__device__ float g_t[4][R][64];
// branch outputs, stored [z][b]
__device__ float g_br[R][8];

__device__ __forceinline__ float swish_f(float v) {
    return v / (1.0f + __expf(-v));
}

// One block per network row: blocks 0..223 -> trunk points, 224..231 -> branch rows.
__global__ void mlp_kernel(
    const float* __restrict__ x1, const float* __restrict__ x2,
    const float* __restrict__ x3, const float* __restrict__ x4,
    const float* __restrict__ f,  const float* __restrict__ Bmat,
    const float* __restrict__ tW0, const float* __restrict__ tb0,
    const float* __restrict__ tW1, const float* __restrict__ tb1,
    const float* __restrict__ tW2, const float* __restrict__ tb2,
    const float* __restrict__ tW3, const float* __restrict__ tb3,
    const float* __restrict__ bW0, const float* __restrict__ bb0,
    const float* __restrict__ bW1, const float* __restrict__ bb1,
    const float* __restrict__ bW2, const float* __restrict__ bb2,
    const float* __restrict__ bW3, const float* __restrict__ bb3)
{
    __shared__ float sA[H];
    __shared__ float sB[H];
    const int bid = blockIdx.x;
    const int tid = threadIdx.x;

    if (bid < 224) {
        // ------------------- trunk path -------------------
        const int d = bid >> 6;      // trunk index 0..3
        const int n = bid & 63;      // point index
        const float* xp = (d == 0) ? x1 : (d == 1) ? x2 : (d == 2) ? x3 : x4;
        const float x = xp[n];

        if (tid < NF) {
            float p = x * Bmat[tid];
            sA[tid]      = cosf(p);
            sA[NF + tid] = sinf(p);
        }
        __syncthreads();

        // layer 0: in=128 -> out=256, swish
        {
            const float4* w = (const float4*)(tW0 + ((size_t)(d * H + tid)) * (2 * NF));
            float acc = tb0[d * H + tid];
            #pragma unroll
            for (int q = 0; q < (2 * NF) / 4; q++) {
                float4 wv = w[q];
                acc += wv.x * sA[4 * q] + wv.y * sA[4 * q + 1]
                     + wv.z * sA[4 * q + 2] + wv.w * sA[4 * q + 3];
            }
            sB[tid] = swish_f(acc);
        }
        __syncthreads();

        // layer 1: 256 -> 256, swish (read sB, write sA)
        {
            const float4* w = (const float4*)(tW1 + ((size_t)(d * H + tid)) * H);
            float acc = tb1[d * H + tid];
            #pragma unroll
            for (int q = 0; q < H / 4; q++) {
                float4 wv = w[q];
                acc += wv.x * sB[4 * q] + wv.y * sB[4 * q + 1]
                     + wv.z * sB[4 * q + 2] + wv.w * sB[4 * q + 3];
            }
            sA[tid] = swish_f(acc);
        }
        __syncthreads();

        // layer 2: 256 -> 256, swish (read sA, write sB)
        {
            const float4* w = (const float4*)(tW2 + ((size_t)(d * H + tid)) * H);
            float acc = tb2[d * H + tid];
            #pragma unroll
            for (int q = 0; q < H / 4; q++) {
                float4 wv = w[q];
                acc += wv.x * sA[4 * q] + wv.y * sA[4 * q + 1]
                     + wv.z * sA[4 * q + 2] + wv.w * sA[4 * q + 3];
            }
            sB[tid] = swish_f(acc);
        }
        __syncthreads();

        // layer 3: 256 -> 64, linear (read sB)
        if (tid < R) {
            const float4* w = (const float4*)(tW3 + ((size_t)(d * R + tid)) * H);
            float acc = tb3[d * R + tid];
            #pragma unroll
            for (int q = 0; q < H / 4; q++) {
                float4 wv = w[q];
                acc += wv.x * sB[4 * q] + wv.y * sB[4 * q + 1]
                     + wv.z * sB[4 * q + 2] + wv.w * sB[4 * q + 3];
            }
            g_t[d][tid][n] = acc;   // z-major store
        }
    } else {
        // ------------------- branch path -------------------
        const int rrow = bid - 224;   // batch row 0..7
        sA[tid] = f[rrow * 256 + tid];
        __syncthreads();

        {
            const float4* w = (const float4*)(bW0 + (size_t)tid * 256);
            float acc = bb0[tid];
            #pragma unroll
            for (int q = 0; q < 64; q++) {
                float4 wv = w[q];
                acc += wv.x * sA[4 * q] + wv.y * sA[4 * q + 1]
                     + wv.z * sA[4 * q + 2] + wv.w * sA[4 * q + 3];
            }
            sB[tid] = swish_f(acc);
        }
        __syncthreads();
        {
            const float4* w = (const float4*)(bW1 + (size_t)tid * H);
            float acc = bb1[tid];
            #pragma unroll
            for (int q = 0; q < H / 4; q++) {
                float4 wv = w[q];
                acc += wv.x * sB[4 * q] + wv.y * sB[4 * q + 1]
                     + wv.z * sB[4 * q + 2] + wv.w * sB[4 * q + 3];
            }
            sA[tid] = swish_f(acc);
        }
        __syncthreads();
        {
            const float4* w = (const float4*)(bW2 + (size_t)tid * H);
            float acc = bb2[tid];
            #pragma unroll
            for (int q = 0; q < H / 4; q++) {
                float4 wv = w[q];
                acc += wv.x * sA[4 * q] + wv.y * sA[4 * q + 1]
                     + wv.z * sA[4 * q + 2] + wv.w * sA[4 * q + 3];
            }
            sB[tid] = swish_f(acc);
        }
        __syncthreads();
        if (tid < R) {
            const float4* w = (const float4*)(bW3 + (size_t)tid * H);
            float acc = bb3[tid];
            #pragma unroll
            for (int q = 0; q < H / 4; q++) {
                float4 wv = w[q];
                acc += wv.x * sB[4 * q] + wv.y * sB[4 * q + 1]
                     + wv.z * sB[4 * q + 2] + wv.w * sB[4 * q + 3];
            }
            g_br[tid][rrow] = acc;
        }
    }
}

// ---------------------------------------------------------------------------
// CP expansion GEMM.
// M = (i,j) = 4096 rows, N = (b,k,l) = 16384 cols, K = 64.
// Block tile: BM=64 (one i, all 64 j) x BN=128 (one b, 4 k x 32 l).
// grid = (128, 64):  blockIdx.x -> N tile (b = bx/16, k0 = (bx%16)*4),
//                    blockIdx.y -> i.
// 128 threads, each computes an 8x8 register tile.
// smem: us[64][64] + ws[64][128] = 48 KB exactly (static limit).
// ---------------------------------------------------------------------------
__global__ __launch_bounds__(128, 4)
void cp_kernel(float* __restrict__ out)
{
    __shared__ float us[R][64];    // us[z][j]  = t1[i][z] * t2[j][z]
    __shared__ float ws[R][128];   // ws[z][c]  = br[b][z] * t3[k][z] * t4[l][z]

    const int bx = blockIdx.x;
    const int iy = blockIdx.y;          // i index
    const int bb = bx >> 4;             // batch index 0..7
    const int k0 = (bx & 15) << 2;      // k base, 4 consecutive k
    const int tid = threadIdx.x;

    // fill us: 4096 elements, consecutive threads -> consecutive j (no conflicts)
    #pragma unroll
    for (int it = 0; it < 32; it++) {
        int idx = tid + it * 128;
        int z = idx >> 6, j = idx & 63;
        us[z][j] = g_t[0][z][iy] * g_t[1][z][j];
    }
    // fill ws: 8192 elements, consecutive threads -> consecutive c
    #pragma unroll
    for (int it = 0; it < 64; it++) {
        int idx = tid + it * 128;
        int z = idx >> 7, c = idx & 127;
        int kk = k0 + (c >> 5);
        int l  = c & 31;
        ws[z][c] = g_br[z][bb] * g_t[2][z][kk] * g_t[3][z][l];
    }
    __syncthreads();

    const int tx = tid & 15;   // col group: cols tx*8 .. tx*8+7
    const int ty = tid >> 4;   // row group: rows ty*8 .. ty*8+7

    float acc[8][8];
    #pragma unroll
    for (int p = 0; p < 8; p++)
        #pragma unroll
        for (int q = 0; q < 8; q++) acc[p][q] = 0.0f;

    #pragma unroll 8
    for (int k = 0; k < R; k++) {
        float4 a0 = *(const float4*)&us[k][ty * 8];
        float4 a1 = *(const float4*)&us[k][ty * 8 + 4];
        float4 b0 = *(const float4*)&ws[k][tx * 8];
        float4 b1 = *(const float4*)&ws[k][tx * 8 + 4];
        float av[8] = {a0.x, a0.y, a0.z, a0.w, a1.x, a1.y, a1.z, a1.w};
        float bv[8] = {b0.x, b0.y, b0.z, b0.w, b1.x, b1.y, b1.z, b1.w};
        #pragma unroll
        for (int p = 0; p < 8; p++)
            #pragma unroll
            for (int q = 0; q < 8; q++)
                acc[p][q] = fmaf(av[p], bv[q], acc[p][q]);
    }

    // epilogue: out[(((b*64+i)*64+j)*64+k)*32+l]
    const int c0 = tx * 8;
    const int kq = k0 + (c0 >> 5);
    const int l0 = c0 & 31;
    const size_t base = (((size_t)bb * 64 + iy) * 64) * 2048 + (size_t)kq * 32 + l0;
    #pragma unroll
    for (int dr = 0; dr < 8; dr++) {
        int j = ty * 8 + dr;
        float* p = out + base + (size_t)j * 2048;
        *(float4*)(p)     = make_float4(acc[dr][0], acc[dr][1], acc[dr][2], acc[dr][3]);
        *(float4*)(p + 4) = make_float4(acc[dr][4], acc[dr][5], acc[dr][6], acc[dr][7]);
    }
}

extern "C" void kernel_launch(void* const* d_in, const int* in_sizes, int n_in,
                              void* d_out, int out_size)
{
    const float* x1  = (const float*)d_in[0];
    const float* x2  = (const float*)d_in[1];
    const float* x3  = (const float*)d_in[2];
    const float* x4  = (const float*)d_in[3];
    const float* f   = (const float*)d_in[4];
    const float* Bm  = (const float*)d_in[5];
    const float* tW0 = (const float*)d_in[6];
    const float* tb0 = (const float*)d_in[7];
    const float* tW1 = (const float*)d_in[8];
    const float* tb1 = (const float*)d_in[9];
    const float* tW2 = (const float*)d_in[10];
    const float* tb2 = (const float*)d_in[11];
    const float* tW3 = (const float*)d_in[12];
    const float* tb3 = (const float*)d_in[13];
    const float* bW0 = (const float*)d_in[14];
    const float* bb0 = (const float*)d_in[15];
    const float* bW1 = (const float*)d_in[16];
    const float* bb1 = (const float*)d_in[17];
    const float* bW2 = (const float*)d_in[18];
    const float* bb2 = (const float*)d_in[19];
    const float* bW3 = (const float*)d_in[20];
    const float* bb3 = (const float*)d_in[21];

    mlp_kernel<<<232, 256>>>(x1, x2, x3, x4, f, Bm,
                             tW0, tb0, tW1, tb1, tW2, tb2, tW3, tb3,
                             bW0, bb0, bW1, bb1, bW2, bb2, bW3, bb3);

    dim3 grid(128, 64);
    cp_kernel<<<grid, 128>>>((float*)d_out);
}

// round 2
// speedup vs baseline: 1.1318x; 1.1318x over previous
#include <cuda_runtime.h>
#include <cuda_bf16.h>
#include <math.h>

// ---------------------------------------------------------------------------
// DeepOHeat_ST: 4 trunk MLPs + branch MLP -> rank-64 CP outer product.
//
// Stage 1 (mlp_kernel): trunk outputs t[d][z][n] (z-major), branch br[z][b].
// Stage 2 (cp_kernel): out[b,i,j,k,l] = sum_z (t1[i,z]*t2[j,z]) *
//   (br[b,z]*t3[k,z]*t4[l,z])  == 4096x16384x64 fp32 GEMM.
//   v2: 128x128 block tile, 16x8 thread tile, fma.rn.f32x2 packed math.
// ---------------------------------------------------------------------------

#define H 256
#define R 64
#define NF 64

// scratch: trunk outputs, stored [trunk][z][n]  (trunk 3 only n<32 valid)
__device__ float g_t[4][R][64];
// branch outputs, stored [z][b]
__device__ float g_br[R][8];

__device__ __forceinline__ float swish_f(float v) {
    return v / (1.0f + __expf(-v));
}

// One block per network row: blocks 0..223 -> trunk points, 224..231 -> branch rows.
__global__ void mlp_kernel(
    const float* __restrict__ x1, const float* __restrict__ x2,
    const float* __restrict__ x3, const float* __restrict__ x4,
    const float* __restrict__ f,  const float* __restrict__ Bmat,
    const float* __restrict__ tW0, const float* __restrict__ tb0,
    const float* __restrict__ tW1, const float* __restrict__ tb1,
    const float* __restrict__ tW2, const float* __restrict__ tb2,
    const float* __restrict__ tW3, const float* __restrict__ tb3,
    const float* __restrict__ bW0, const float* __restrict__ bb0,
    const float* __restrict__ bW1, const float* __restrict__ bb1,
    const float* __restrict__ bW2, const float* __restrict__ bb2,
    const float* __restrict__ bW3, const float* __restrict__ bb3)
{
    __shared__ float sA[H];
    __shared__ float sB[H];
    const int bid = blockIdx.x;
    const int tid = threadIdx.x;

    if (bid < 224) {
        const int d = bid >> 6;
        const int n = bid & 63;
        const float* xp = (d == 0) ? x1 : (d == 1) ? x2 : (d == 2) ? x3 : x4;
        const float x = xp[n];

        if (tid < NF) {
            float p = x * Bmat[tid];
            sA[tid]      = cosf(p);
            sA[NF + tid] = sinf(p);
        }
        __syncthreads();

        {
            const float4* w = (const float4*)(tW0 + ((size_t)(d * H + tid)) * (2 * NF));
            float acc = tb0[d * H + tid];
            #pragma unroll
            for (int q = 0; q < (2 * NF) / 4; q++) {
                float4 wv = w[q];
                acc += wv.x * sA[4 * q] + wv.y * sA[4 * q + 1]
                     + wv.z * sA[4 * q + 2] + wv.w * sA[4 * q + 3];
            }
            sB[tid] = swish_f(acc);
        }
        __syncthreads();
        {
            const float4* w = (const float4*)(tW1 + ((size_t)(d * H + tid)) * H);
            float acc = tb1[d * H + tid];
            #pragma unroll
            for (int q = 0; q < H / 4; q++) {
                float4 wv = w[q];
                acc += wv.x * sB[4 * q] + wv.y * sB[4 * q + 1]
                     + wv.z * sB[4 * q + 2] + wv.w * sB[4 * q + 3];
            }
            sA[tid] = swish_f(acc);
        }
        __syncthreads();
        {
            const float4* w = (const float4*)(tW2 + ((size_t)(d * H + tid)) * H);
            float acc = tb2[d * H + tid];
            #pragma unroll
            for (int q = 0; q < H / 4; q++) {
                float4 wv = w[q];
                acc += wv.x * sA[4 * q] + wv.y * sA[4 * q + 1]
                     + wv.z * sA[4 * q + 2] + wv.w * sA[4 * q + 3];
            }
            sB[tid] = swish_f(acc);
        }
        __syncthreads();
        if (tid < R) {
            const float4* w = (const float4*)(tW3 + ((size_t)(d * R + tid)) * H);
            float acc = tb3[d * R + tid];
            #pragma unroll
            for (int q = 0; q < H / 4; q++) {
                float4 wv = w[q];
                acc += wv.x * sB[4 * q] + wv.y * sB[4 * q + 1]
                     + wv.z * sB[4 * q + 2] + wv.w * sB[4 * q + 3];
            }
            g_t[d][tid][n] = acc;
        }
    } else {
        const int rrow = bid - 224;
        sA[tid] = f[rrow * 256 + tid];
        __syncthreads();
        {
            const float4* w = (const float4*)(bW0 + (size_t)tid * 256);
            float acc = bb0[tid];
            #pragma unroll
            for (int q = 0; q < 64; q++) {
                float4 wv = w[q];
                acc += wv.x * sA[4 * q] + wv.y * sA[4 * q + 1]
                     + wv.z * sA[4 * q + 2] + wv.w * sA[4 * q + 3];
            }
            sB[tid] = swish_f(acc);
        }
        __syncthreads();
        {
            const float4* w = (const float4*)(bW1 + (size_t)tid * H);
            float acc = bb1[tid];
            #pragma unroll
            for (int q = 0; q < H / 4; q++) {
                float4 wv = w[q];
                acc += wv.x * sB[4 * q] + wv.y * sB[4 * q + 1]
                     + wv.z * sB[4 * q + 2] + wv.w * sB[4 * q + 3];
            }
            sA[tid] = swish_f(acc);
        }
        __syncthreads();
        {
            const float4* w = (const float4*)(bW2 + (size_t)tid * H);
            float acc = bb2[tid];
            #pragma unroll
            for (int q = 0; q < H / 4; q++) {
                float4 wv = w[q];
                acc += wv.x * sA[4 * q] + wv.y * sA[4 * q + 1]
                     + wv.z * sA[4 * q + 2] + wv.w * sA[4 * q + 3];
            }
            sB[tid] = swish_f(acc);
        }
        __syncthreads();
        if (tid < R) {
            const float4* w = (const float4*)(bW3 + (size_t)tid * H);
            float acc = bb3[tid];
            #pragma unroll
            for (int q = 0; q < H / 4; q++) {
                float4 wv = w[q];
                acc += wv.x * sB[4 * q] + wv.y * sB[4 * q + 1]
                     + wv.z * sB[4 * q + 2] + wv.w * sB[4 * q + 3];
            }
            g_br[tid][rrow] = acc;
        }
    }
}

// ---------------------------------------------------------------------------
// CP expansion GEMM v2.
// M = (i,j) = 4096 rows, N = (b,k,l) = 16384 cols, K = 64.
// Block tile: BM=128 (two i, all 64 j) x BN=128 (one b, 4 k x 32 l).
// grid = (128, 32). 128 threads; thread tile = 16 rows x 8 cols.
// Row pairs packed into f32x2; fma.rn.f32x2 doubles fp32 FMA throughput.
// smem: us[64][128] + ws[64][128] = 64 KB dynamic.
// ---------------------------------------------------------------------------
__global__ __launch_bounds__(128, 3)
void cp_kernel(float* __restrict__ out)
{
    extern __shared__ float smem[];
    float (*us)[128] = (float (*)[128])smem;               // us[z][row]
    float (*ws)[128] = (float (*)[128])(smem + 64 * 128);  // ws[z][col]

    const int bx  = blockIdx.x;
    const int bb  = bx >> 4;            // batch index 0..7
    const int k0  = (bx & 15) << 2;     // k base (4 consecutive k)
    const int i0  = blockIdx.y << 1;    // two consecutive i
    const int tid = threadIdx.x;

    // ---- fill us: us[z][row] = t1[i0 + row/64][z] * t2[row%64][z] ----
    #pragma unroll
    for (int it = 0; it < 16; it++) {
        int idx4 = tid + it * 128;          // float4 index, 0..2047
        int z    = idx4 >> 5;
        int row  = (idx4 & 31) << 2;
        int i    = i0 + (row >> 6);
        int j    = row & 63;
        float  a   = g_t[0][z][i];
        float4 t2v = *(const float4*)&g_t[1][z][j];
        *(float4*)&us[z][row] =
            make_float4(a * t2v.x, a * t2v.y, a * t2v.z, a * t2v.w);
    }
    // ---- fill ws: ws[z][c] = br[b][z] * t3[k0+c/32][z] * t4[c%32][z] ----
    #pragma unroll
    for (int it = 0; it < 16; it++) {
        int idx4 = tid + it * 128;
        int z    = idx4 >> 5;
        int c    = (idx4 & 31) << 2;
        int kk   = k0 + (c >> 5);
        int l    = c & 31;
        float  s   = g_br[z][bb] * g_t[2][z][kk];
        float4 t4v = *(const float4*)&g_t[3][z][l];
        *(float4*)&ws[z][c] =
            make_float4(s * t4v.x, s * t4v.y, s * t4v.z, s * t4v.w);
    }
    __syncthreads();

    const int tx = tid & 15;   // col group: cols tx*8 .. tx*8+7
    const int ty = tid >> 4;   // row group: rows ty*16 .. ty*16+15

    // acc[pp][q]: f32x2 pair = rows (ty*16 + 2*pp, +1), col tx*8+q
    unsigned long long acc[8][8];
    #pragma unroll
    for (int p = 0; p < 8; p++)
        #pragma unroll
        for (int q = 0; q < 8; q++) acc[p][q] = 0ull;

    #pragma unroll 8
    for (int k = 0; k < R; k++) {
        // A operand: 16 rows = 8 natural f32x2 pairs (broadcast within warp)
        ulonglong2 a01 = *(const ulonglong2*)&us[k][ty * 16];
        ulonglong2 a23 = *(const ulonglong2*)&us[k][ty * 16 + 4];
        ulonglong2 a45 = *(const ulonglong2*)&us[k][ty * 16 + 8];
        ulonglong2 a67 = *(const ulonglong2*)&us[k][ty * 16 + 12];
        unsigned long long a2[8] = {a01.x, a01.y, a23.x, a23.y,
                                    a45.x, a45.y, a67.x, a67.y};
        // B operand: 8 cols, duplicated into both f32x2 lanes
        float4 b0 = *(const float4*)&ws[k][tx * 8];
        float4 b1 = *(const float4*)&ws[k][tx * 8 + 4];
        float bw[8] = {b0.x, b0.y, b0.z, b0.w, b1.x, b1.y, b1.z, b1.w};
        unsigned long long bd[8];
        #pragma unroll
        for (int q = 0; q < 8; q++)
            asm("mov.b64 %0, {%1, %1};" : "=l"(bd[q]) : "f"(bw[q]));

        #pragma unroll
        for (int pp = 0; pp < 8; pp++)
            #pragma unroll
            for (int q = 0; q < 8; q++)
                asm("fma.rn.f32x2 %0, %1, %2, %0;"
                    : "+l"(acc[pp][q])
                    : "l"(a2[pp]), "l"(bd[q]));
    }

    // ---- epilogue: out[(((b*64+i)*64+j)*64+k)*32+l] ----
    const int c0 = tx * 8;
    const int kq = k0 + (c0 >> 5);
    const int l0 = c0 & 31;
    #pragma unroll
    for (int pp = 0; pp < 8; pp++) {
        float lo[8], hi[8];
        #pragma unroll
        for (int q = 0; q < 8; q++)
            asm("mov.b64 {%0, %1}, %2;"
                : "=f"(lo[q]), "=f"(hi[q]) : "l"(acc[pp][q]));
        int row0 = ty * 16 + pp * 2;
        {
            int row = row0;
            int i = i0 + (row >> 6);
            int j = row & 63;
            float* p = out + ((((size_t)bb * 64 + i) * 64 + j) * 64 + kq) * 32 + l0;
            *(float4*)(p)     = make_float4(lo[0], lo[1], lo[2], lo[3]);
            *(float4*)(p + 4) = make_float4(lo[4], lo[5], lo[6], lo[7]);
        }
        {
            int row = row0 + 1;
            int i = i0 + (row >> 6);
            int j = row & 63;
            float* p = out + ((((size_t)bb * 64 + i) * 64 + j) * 64 + kq) * 32 + l0;
            *(float4*)(p)     = make_float4(hi[0], hi[1], hi[2], hi[3]);
            *(float4*)(p + 4) = make_float4(hi[4], hi[5], hi[6], hi[7]);
        }
    }
}

extern "C" void kernel_launch(void* const* d_in, const int* in_sizes, int n_in,
                              void* d_out, int out_size)
{
    const float* x1  = (const float*)d_in[0];
    const float* x2  = (const float*)d_in[1];
    const float* x3  = (const float*)d_in[2];
    const float* x4  = (const float*)d_in[3];
    const float* f   = (const float*)d_in[4];
    const float* Bm  = (const float*)d_in[5];
    const float* tW0 = (const float*)d_in[6];
    const float* tb0 = (const float*)d_in[7];
    const float* tW1 = (const float*)d_in[8];
    const float* tb1 = (const float*)d_in[9];
    const float* tW2 = (const float*)d_in[10];
    const float* tb2 = (const float*)d_in[11];
    const float* tW3 = (const float*)d_in[12];
    const float* tb3 = (const float*)d_in[13];
    const float* bW0 = (const float*)d_in[14];
    const float* bb0 = (const float*)d_in[15];
    const float* bW1 = (const float*)d_in[16];
    const float* bb1 = (const float*)d_in[17];
    const float* bW2 = (const float*)d_in[18];
    const float* bb2 = (const float*)d_in[19];
    const float* bW3 = (const float*)d_in[20];
    const float* bb3 = (const float*)d_in[21];

    mlp_kernel<<<232, 256>>>(x1, x2, x3, x4, f, Bm,
                             tW0, tb0, tW1, tb1, tW2, tb2, tW3, tb3,
                             bW0, bb0, bW1, bb1, bW2, bb2, bW3, bb3);

    cudaFuncSetAttribute(cp_kernel,
                         cudaFuncAttributeMaxDynamicSharedMemorySize, 65536);
    dim3 grid(128, 32);
    cp_kernel<<<grid, 128, 65536>>>((float*)d_out);
}

// round 5
// speedup vs baseline: 1.6959x; 1.4984x over previous
#include <cuda_runtime.h>
#include <cuda_bf16.h>
#include <math.h>
#include <stdint.h>

// ---------------------------------------------------------------------------
// DeepOHeat_ST: 4 trunk MLPs + branch MLP -> rank-64 CP outer product.
//
// Stage 1 (mlp_kernel): trunk outputs g_tn[d][n][z] (n-major), branch g_brn.
// Stage 2 (pack_kernel): bf16 hi/lo split operands  A'=[uh|ul], B'=[wh|wl]
// Stage 3 (gemm_kernel): out = u @ w^T via mma.sync bf16, fp32 accum,
//     3-pass split:  uh*wh + ul*wh + uh*wl   (residual ul*wl ~ 2^-16)
//     M=4096, N=16384. 128x128 CTA tile, 4096 CTAs.
// ---------------------------------------------------------------------------

#define H 256
#define R 64
#define NF 64

__device__ float g_tn[4][64][64];            // [trunk][point][z]
__device__ float g_brn[8][64];               // [batch][z]
__device__ __nv_bfloat16 g_A[4096 * 128];    // [m][k]  k: 0..63 hi, 64..127 lo
__device__ __nv_bfloat16 g_B[16384 * 128];   // [n][k]

__device__ __forceinline__ float swish_f(float v) {
    return v / (1.0f + __expf(-v));
}
__device__ __forceinline__ uint32_t smem_u32(const void* p) {
    uint32_t a;
    asm("{ .reg .u64 t; cvta.to.shared.u64 t, %1; cvt.u32.u64 %0, t; }"
        : "=r"(a) : "l"(p));
    return a;
}

// ======================= Stage 1: MLPs =====================================
__global__ void mlp_kernel(
    const float* __restrict__ x1, const float* __restrict__ x2,
    const float* __restrict__ x3, const float* __restrict__ x4,
    const float* __restrict__ f,  const float* __restrict__ Bmat,
    const float* __restrict__ tW0, const float* __restrict__ tb0,
    const float* __restrict__ tW1, const float* __restrict__ tb1,
    const float* __restrict__ tW2, const float* __restrict__ tb2,
    const float* __restrict__ tW3, const float* __restrict__ tb3,
    const float* __restrict__ bW0, const float* __restrict__ bb0,
    const float* __restrict__ bW1, const float* __restrict__ bb1,
    const float* __restrict__ bW2, const float* __restrict__ bb2,
    const float* __restrict__ bW3, const float* __restrict__ bb3)
{
    __shared__ float sA[H];
    __shared__ float sB[H];
    const int bid = blockIdx.x;
    const int tid = threadIdx.x;

    if (bid < 224) {
        const int d = bid >> 6;
        const int n = bid & 63;
        if (d == 3 && n >= 32) return;      // trunk 3 has only 32 points
        const float* xp = (d == 0) ? x1 : (d == 1) ? x2 : (d == 2) ? x3 : x4;
        const float x = xp[n];

        if (tid < NF) {
            float p = x * Bmat[tid];
            sA[tid]      = cosf(p);
            sA[NF + tid] = sinf(p);
        }
        __syncthreads();
        {
            const float4* w = (const float4*)(tW0 + ((size_t)(d * H + tid)) * (2 * NF));
            float acc = tb0[d * H + tid];
            #pragma unroll
            for (int q = 0; q < (2 * NF) / 4; q++) {
                float4 wv = w[q];
                acc += wv.x * sA[4 * q] + wv.y * sA[4 * q + 1]
                     + wv.z * sA[4 * q + 2] + wv.w * sA[4 * q + 3];
            }
            sB[tid] = swish_f(acc);
        }
        __syncthreads();
        {
            const float4* w = (const float4*)(tW1 + ((size_t)(d * H + tid)) * H);
            float acc = tb1[d * H + tid];
            #pragma unroll
            for (int q = 0; q < H / 4; q++) {
                float4 wv = w[q];
                acc += wv.x * sB[4 * q] + wv.y * sB[4 * q + 1]
                     + wv.z * sB[4 * q + 2] + wv.w * sB[4 * q + 3];
            }
            sA[tid] = swish_f(acc);
        }
        __syncthreads();
        {
            const float4* w = (const float4*)(tW2 + ((size_t)(d * H + tid)) * H);
            float acc = tb2[d * H + tid];
            #pragma unroll
            for (int q = 0; q < H / 4; q++) {
                float4 wv = w[q];
                acc += wv.x * sA[4 * q] + wv.y * sA[4 * q + 1]
                     + wv.z * sA[4 * q + 2] + wv.w * sA[4 * q + 3];
            }
            sB[tid] = swish_f(acc);
        }
        __syncthreads();
        if (tid < R) {
            const float4* w = (const float4*)(tW3 + ((size_t)(d * R + tid)) * H);
            float acc = tb3[d * R + tid];
            #pragma unroll
            for (int q = 0; q < H / 4; q++) {
                float4 wv = w[q];
                acc += wv.x * sB[4 * q] + wv.y * sB[4 * q + 1]
                     + wv.z * sB[4 * q + 2] + wv.w * sB[4 * q + 3];
            }
            g_tn[d][n][tid] = acc;
        }
    } else {
        const int rrow = bid - 224;
        sA[tid] = f[rrow * 256 + tid];
        __syncthreads();
        {
            const float4* w = (const float4*)(bW0 + (size_t)tid * 256);
            float acc = bb0[tid];
            #pragma unroll
            for (int q = 0; q < 64; q++) {
                float4 wv = w[q];
                acc += wv.x * sA[4 * q] + wv.y * sA[4 * q + 1]
                     + wv.z * sA[4 * q + 2] + wv.w * sA[4 * q + 3];
            }
            sB[tid] = swish_f(acc);
        }
        __syncthreads();
        {
            const float4* w = (const float4*)(bW1 + (size_t)tid * H);
            float acc = bb1[tid];
            #pragma unroll
            for (int q = 0; q < H / 4; q++) {
                float4 wv = w[q];
                acc += wv.x * sB[4 * q] + wv.y * sB[4 * q + 1]
                     + wv.z * sB[4 * q + 2] + wv.w * sB[4 * q + 3];
            }
            sA[tid] = swish_f(acc);
        }
        __syncthreads();
        {
            const float4* w = (const float4*)(bW2 + (size_t)tid * H);
            float acc = bb2[tid];
            #pragma unroll
            for (int q = 0; q < H / 4; q++) {
                float4 wv = w[q];
                acc += wv.x * sA[4 * q] + wv.y * sA[4 * q + 1]
                     + wv.z * sA[4 * q + 2] + wv.w * sA[4 * q + 3];
            }
            sB[tid] = swish_f(acc);
        }
        __syncthreads();
        if (tid < R) {
            const float4* w = (const float4*)(bW3 + (size_t)tid * H);
            float acc = bb3[tid];
            #pragma unroll
            for (int q = 0; q < H / 4; q++) {
                float4 wv = w[q];
                acc += wv.x * sB[4 * q] + wv.y * sB[4 * q + 1]
                     + wv.z * sB[4 * q + 2] + wv.w * sB[4 * q + 3];
            }
            g_brn[rrow][tid] = acc;
        }
    }
}

// ======================= Stage 2: bf16 split pack ==========================
__device__ __forceinline__ void split_store(__nv_bfloat16* row, int z0, float4 u) {
    float uv[4] = {u.x, u.y, u.z, u.w};
    __nv_bfloat16 h[4], lo[4];
    #pragma unroll
    for (int q = 0; q < 4; q++) {
        h[q]  = __float2bfloat16(uv[q]);
        lo[q] = __float2bfloat16(uv[q] - __bfloat162float(h[q]));
    }
    *(__nv_bfloat162*)(row + z0)          = __nv_bfloat162(h[0], h[1]);
    *(__nv_bfloat162*)(row + z0 + 2)      = __nv_bfloat162(h[2], h[3]);
    *(__nv_bfloat162*)(row + 64 + z0)     = __nv_bfloat162(lo[0], lo[1]);
    *(__nv_bfloat162*)(row + 64 + z0 + 2) = __nv_bfloat162(lo[2], lo[3]);
}

__global__ void pack_kernel()
{
    int id = blockIdx.x * 256 + threadIdx.x;
    if (id < 65536) {
        int m = id >> 4, z0 = (id & 15) << 2;
        int i = m >> 6, j = m & 63;
        float4 a = *(const float4*)&g_tn[0][i][z0];
        float4 c = *(const float4*)&g_tn[1][j][z0];
        split_store(g_A + (size_t)m * 128, z0,
                    make_float4(a.x * c.x, a.y * c.y, a.z * c.z, a.w * c.w));
    } else {
        id -= 65536;                       // [0, 262144)
        int n = id >> 4, z0 = (id & 15) << 2;
        int b = n >> 11, k = (n >> 5) & 63, l = n & 31;
        float4 p = *(const float4*)&g_brn[b][z0];
        float4 q = *(const float4*)&g_tn[2][k][z0];
        float4 r = *(const float4*)&g_tn[3][l][z0];
        split_store(g_B + (size_t)n * 128, z0,
                    make_float4(p.x * q.x * r.x, p.y * q.y * r.y,
                                p.z * q.z * r.z, p.w * q.w * r.w));
    }
}

// ======================= Stage 3: mma.sync bf16 GEMM =======================
// CTA tile 128(M) x 128(N), physical K=128 staged once; 3 passes of 4
// k-steps each realize the hi/lo split product.
// smem: A 32KB + B 32KB, XOR-swizzled 16B chunks -> conflict-free ldmatrix.
// 8 warps, 2(M) x 4(N), warp tile 64x32, atoms m16n8k16.
__global__ __launch_bounds__(256, 2)
void gemm_kernel(float* __restrict__ out)
{
    extern __shared__ __align__(128) char smem[];
    char* As = smem;            // [128 rows][256 B]
    char* Bs = smem + 32768;    // [128 rows][256 B]
    const int tid  = threadIdx.x;
    const int wid  = tid >> 5;
    const int lane = tid & 31;
    const int m0 = blockIdx.y * 128;
    const int n0 = blockIdx.x * 128;

    // ---- stage tiles ----
    const __nv_bfloat16* Ag = g_A + (size_t)m0 * 128;
    const __nv_bfloat16* Bg = g_B + (size_t)n0 * 128;
    #pragma unroll
    for (int it = 0; it < 8; it++) {
        int idx = tid + it * 256;        // 0..2047
        int row = idx >> 4;
        int kc  = idx & 15;
        *(uint4*)(As + row * 256 + ((kc ^ (row & 7)) << 4)) =
            *(const uint4*)(Ag + row * 128 + kc * 8);
    }
    #pragma unroll
    for (int it = 0; it < 8; it++) {
        int idx = tid + it * 256;
        int row = idx >> 4;
        int kc  = idx & 15;
        *(uint4*)(Bs + row * 256 + ((kc ^ (row & 7)) << 4)) =
            *(const uint4*)(Bg + row * 128 + kc * 8);
    }
    __syncthreads();

    const int warp_m = wid & 1;          // 0..1  (64 rows each)
    const int warp_n = wid >> 1;         // 0..3  (32 cols each)
    const uint32_t a_base = smem_u32(As);
    const uint32_t b_base = smem_u32(Bs);

    float acc[4][4][4];
    #pragma unroll
    for (int am = 0; am < 4; am++)
        #pragma unroll
        for (int bn = 0; bn < 4; bn++)
            #pragma unroll
            for (int q = 0; q < 4; q++) acc[am][bn][q] = 0.0f;

    // 3 passes: (A hi, B hi), (A lo, B hi), (A hi, B lo)
    #pragma unroll
    for (int pass = 0; pass < 3; pass++) {
        const int a_off = (pass == 1) ? 4 : 0;   // k-step offset (16 elems each)
        const int b_off = (pass == 2) ? 4 : 0;
        #pragma unroll
        for (int ks = 0; ks < 4; ks++) {
            uint32_t a[4][4], b[4][2];
            #pragma unroll
            for (int am = 0; am < 4; am++) {
                int row = warp_m * 64 + am * 16 + (lane & 15);
                int kc  = (a_off + ks) * 2 + (lane >> 4);
                uint32_t addr = a_base + row * 256 + ((kc ^ (row & 7)) << 4);
                asm volatile("ldmatrix.sync.aligned.m8n8.x4.shared.b16 {%0,%1,%2,%3}, [%4];"
                             : "=r"(a[am][0]), "=r"(a[am][1]),
                               "=r"(a[am][2]), "=r"(a[am][3]) : "r"(addr));
            }
            #pragma unroll
            for (int bn = 0; bn < 4; bn++) {
                int row = warp_n * 32 + bn * 8 + (lane & 7);
                int kc  = (b_off + ks) * 2 + ((lane >> 3) & 1);
                uint32_t addr = b_base + row * 256 + ((kc ^ (row & 7)) << 4);
                asm volatile("ldmatrix.sync.aligned.m8n8.x2.shared.b16 {%0,%1}, [%2];"
                             : "=r"(b[bn][0]), "=r"(b[bn][1]) : "r"(addr));
            }
            #pragma unroll
            for (int am = 0; am < 4; am++)
                #pragma unroll
                for (int bn = 0; bn < 4; bn++)
                    asm volatile(
                        "mma.sync.aligned.m16n8k16.row.col.f32.bf16.bf16.f32 "
                        "{%0,%1,%2,%3}, {%4,%5,%6,%7}, {%8,%9}, {%0,%1,%2,%3};"
                        : "+f"(acc[am][bn][0]), "+f"(acc[am][bn][1]),
                          "+f"(acc[am][bn][2]), "+f"(acc[am][bn][3])
                        : "r"(a[am][0]), "r"(a[am][1]), "r"(a[am][2]), "r"(a[am][3]),
                          "r"(b[bn][0]), "r"(b[bn][1]));
        }
    }

    // ---- epilogue: out[(((b*64+i)*64+j)*64+k)*32+l] ----
    #pragma unroll
    for (int am = 0; am < 4; am++) {
        #pragma unroll
        for (int bn = 0; bn < 4; bn++) {
            int mg = m0 + warp_m * 64 + am * 16 + (lane >> 2);
            int ng = n0 + warp_n * 32 + bn * 8 + (lane & 3) * 2;
            int bi = ng >> 11, rem = ng & 2047;
            {
                int i = mg >> 6, j = mg & 63;
                float* p = out + (((size_t)bi * 64 + i) * 64 + j) * 2048 + rem;
                *(float2*)p = make_float2(acc[am][bn][0], acc[am][bn][1]);
            }
            {
                int mg2 = mg + 8;
                int i = mg2 >> 6, j = mg2 & 63;
                float* p = out + (((size_t)bi * 64 + i) * 64 + j) * 2048 + rem;
                *(float2*)p = make_float2(acc[am][bn][2], acc[am][bn][3]);
            }
        }
    }
}

// ======================= launch ============================================
extern "C" void kernel_launch(void* const* d_in, const int* in_sizes, int n_in,
                              void* d_out, int out_size)
{
    const float* x1  = (const float*)d_in[0];
    const float* x2  = (const float*)d_in[1];
    const float* x3  = (const float*)d_in[2];
    const float* x4  = (const float*)d_in[3];
    const float* f   = (const float*)d_in[4];
    const float* Bm  = (const float*)d_in[5];
    const float* tW0 = (const float*)d_in[6];
    const float* tb0 = (const float*)d_in[7];
    const float* tW1 = (const float*)d_in[8];
    const float* tb1 = (const float*)d_in[9];
    const float* tW2 = (const float*)d_in[10];
    const float* tb2 = (const float*)d_in[11];
    const float* tW3 = (const float*)d_in[12];
    const float* tb3 = (const float*)d_in[13];
    const float* bW0 = (const float*)d_in[14];
    const float* bb0 = (const float*)d_in[15];
    const float* bW1 = (const float*)d_in[16];
    const float* bb1 = (const float*)d_in[17];
    const float* bW2 = (const float*)d_in[18];
    const float* bb2 = (const float*)d_in[19];
    const float* bW3 = (const float*)d_in[20];
    const float* bb3 = (const float*)d_in[21];

    mlp_kernel<<<232, 256>>>(x1, x2, x3, x4, f, Bm,
                             tW0, tb0, tW1, tb1, tW2, tb2, tW3, tb3,
                             bW0, bb0, bW1, bb1, bW2, bb2, bW3, bb3);

    pack_kernel<<<1280, 256>>>();

    cudaFuncSetAttribute(gemm_kernel,
                         cudaFuncAttributeMaxDynamicSharedMemorySize, 65536);
    dim3 grid(128, 32);
    gemm_kernel<<<grid, 256, 65536>>>((float*)d_out);
}

// round 6
// speedup vs baseline: 1.6962x; 1.0002x over previous
#include <cuda_runtime.h>
#include <cuda_bf16.h>
#include <math.h>
#include <stdint.h>

// ---------------------------------------------------------------------------
// DeepOHeat_ST: 4 trunk MLPs + branch MLP -> rank-64 CP outer product.
//
// Stage 1 (mlp_kernel): batched-point MLPs. Trunk blocks process 4 points,
//   branch blocks 4 rows; weight rows loaded once per block and reused.
// Stage 2 (pack_kernel): bf16 hi/lo split operands  A'=[uh|ul], B'=[wh|wl]
// Stage 3 (gemm_kernel): out = u @ w^T via mma.sync bf16, fp32 accum,
//     3-pass split:  uh*wh + ul*wh + uh*wl   (residual ul*wl ~ 2^-16)
// ---------------------------------------------------------------------------

#define H 256
#define R 64
#define NF 64

__device__ float g_tn[4][64][64];            // [trunk][point][z]
__device__ float g_brn[8][64];               // [batch][z]
__device__ __nv_bfloat16 g_A[4096 * 128];    // [m][k]  k: 0..63 hi, 64..127 lo
__device__ __nv_bfloat16 g_B[16384 * 128];   // [n][k]

__device__ __forceinline__ float swish_f(float v) {
    return v / (1.0f + __expf(-v));
}
__device__ __forceinline__ uint32_t smem_u32(const void* p) {
    uint32_t a;
    asm("{ .reg .u64 t; cvta.to.shared.u64 t, %1; cvt.u32.u64 %0, t; }"
        : "=r"(a) : "l"(p));
    return a;
}
__device__ __forceinline__ float dot4(float4 w, const float* s) {
    return w.x * s[0] + w.y * s[1] + w.z * s[2] + w.w * s[3];
}

// ======================= Stage 1: batched MLPs =============================
// Blocks 0..47: trunks 0..2, 4 points each (bid>>4 = trunk, (bid&15)*4 = n0)
// Blocks 48..55: trunk 3, 4 points each
// Blocks 56..57: branch, 4 rows each
__global__ __launch_bounds__(256, 2)
void mlp_kernel(
    const float* __restrict__ x1, const float* __restrict__ x2,
    const float* __restrict__ x3, const float* __restrict__ x4,
    const float* __restrict__ f,  const float* __restrict__ Bmat,
    const float* __restrict__ tW0, const float* __restrict__ tb0,
    const float* __restrict__ tW1, const float* __restrict__ tb1,
    const float* __restrict__ tW2, const float* __restrict__ tb2,
    const float* __restrict__ tW3, const float* __restrict__ tb3,
    const float* __restrict__ bW0, const float* __restrict__ bb0,
    const float* __restrict__ bW1, const float* __restrict__ bb1,
    const float* __restrict__ bW2, const float* __restrict__ bb2,
    const float* __restrict__ bW3, const float* __restrict__ bb3)
{
    __shared__ float sA[4][256];
    __shared__ float sB[4][256];
    const int bid = blockIdx.x;
    const int tid = threadIdx.x;

    if (bid < 56) {
        // ---------------- trunk path: 4 points ----------------
        int d, n0;
        if (bid < 48) { d = bid >> 4; n0 = (bid & 15) << 2; }
        else          { d = 3;        n0 = (bid - 48) << 2; }
        const float* xp = (d == 0) ? x1 : (d == 1) ? x2 : (d == 2) ? x3 : x4;

        // Fourier features: sA[p][0:128]
        #pragma unroll
        for (int it = 0; it < 2; it++) {
            int idx = tid + it * 256;        // 0..511
            int p = idx >> 7, ff = idx & 127;
            float x = xp[n0 + p];
            sA[p][ff] = (ff < 64) ? cosf(x * Bmat[ff]) : sinf(x * Bmat[ff - 64]);
        }
        __syncthreads();

        // L0: 128 -> 256, swish
        {
            const float4* w = (const float4*)(tW0 + ((size_t)(d * H + tid)) * 128);
            float bias = tb0[d * H + tid];
            float acc[4] = {bias, bias, bias, bias};
            #pragma unroll
            for (int q = 0; q < 32; q += 8) {
                float4 wv[8];
                #pragma unroll
                for (int u = 0; u < 8; u++) wv[u] = w[q + u];
                #pragma unroll
                for (int u = 0; u < 8; u++)
                    #pragma unroll
                    for (int p = 0; p < 4; p++)
                        acc[p] += dot4(wv[u], &sA[p][4 * (q + u)]);
            }
            #pragma unroll
            for (int p = 0; p < 4; p++) sB[p][tid] = swish_f(acc[p]);
        }
        __syncthreads();

        // L1: 256 -> 256, swish
        {
            const float4* w = (const float4*)(tW1 + ((size_t)(d * H + tid)) * 256);
            float bias = tb1[d * H + tid];
            float acc[4] = {bias, bias, bias, bias};
            #pragma unroll
            for (int q = 0; q < 64; q += 8) {
                float4 wv[8];
                #pragma unroll
                for (int u = 0; u < 8; u++) wv[u] = w[q + u];
                #pragma unroll
                for (int u = 0; u < 8; u++)
                    #pragma unroll
                    for (int p = 0; p < 4; p++)
                        acc[p] += dot4(wv[u], &sB[p][4 * (q + u)]);
            }
            #pragma unroll
            for (int p = 0; p < 4; p++) sA[p][tid] = swish_f(acc[p]);
        }
        __syncthreads();

        // L2: 256 -> 256, swish
        {
            const float4* w = (const float4*)(tW2 + ((size_t)(d * H + tid)) * 256);
            float bias = tb2[d * H + tid];
            float acc[4] = {bias, bias, bias, bias};
            #pragma unroll
            for (int q = 0; q < 64; q += 8) {
                float4 wv[8];
                #pragma unroll
                for (int u = 0; u < 8; u++) wv[u] = w[q + u];
                #pragma unroll
                for (int u = 0; u < 8; u++)
                    #pragma unroll
                    for (int p = 0; p < 4; p++)
                        acc[p] += dot4(wv[u], &sA[p][4 * (q + u)]);
            }
            #pragma unroll
            for (int p = 0; p < 4; p++) sB[p][tid] = swish_f(acc[p]);
        }
        __syncthreads();

        // L3: 256 -> 64, linear. tid = (pg, r): r = tid&63, point pg = tid>>6
        {
            int r = tid & 63, pg = tid >> 6;
            const float4* w = (const float4*)(tW3 + ((size_t)(d * R + r)) * 256);
            float acc = tb3[d * R + r];
            #pragma unroll
            for (int q = 0; q < 64; q += 8) {
                float4 wv[8];
                #pragma unroll
                for (int u = 0; u < 8; u++) wv[u] = w[q + u];
                #pragma unroll
                for (int u = 0; u < 8; u++)
                    acc += dot4(wv[u], &sB[pg][4 * (q + u)]);
            }
            g_tn[d][n0 + pg][r] = acc;
        }
    } else {
        // ---------------- branch path: 4 rows ----------------
        const int r0 = (bid - 56) << 2;

        #pragma unroll
        for (int it = 0; it < 4; it++) {
            int idx = tid + it * 256;        // 0..1023
            int p = idx >> 8, ff = idx & 255;
            sA[p][ff] = f[(r0 + p) * 256 + ff];
        }
        __syncthreads();

        // L0: 256 -> 256, swish
        {
            const float4* w = (const float4*)(bW0 + (size_t)tid * 256);
            float bias = bb0[tid];
            float acc[4] = {bias, bias, bias, bias};
            #pragma unroll
            for (int q = 0; q < 64; q += 8) {
                float4 wv[8];
                #pragma unroll
                for (int u = 0; u < 8; u++) wv[u] = w[q + u];
                #pragma unroll
                for (int u = 0; u < 8; u++)
                    #pragma unroll
                    for (int p = 0; p < 4; p++)
                        acc[p] += dot4(wv[u], &sA[p][4 * (q + u)]);
            }
            #pragma unroll
            for (int p = 0; p < 4; p++) sB[p][tid] = swish_f(acc[p]);
        }
        __syncthreads();

        // L1
        {
            const float4* w = (const float4*)(bW1 + (size_t)tid * 256);
            float bias = bb1[tid];
            float acc[4] = {bias, bias, bias, bias};
            #pragma unroll
            for (int q = 0; q < 64; q += 8) {
                float4 wv[8];
                #pragma unroll
                for (int u = 0; u < 8; u++) wv[u] = w[q + u];
                #pragma unroll
                for (int u = 0; u < 8; u++)
                    #pragma unroll
                    for (int p = 0; p < 4; p++)
                        acc[p] += dot4(wv[u], &sB[p][4 * (q + u)]);
            }
            #pragma unroll
            for (int p = 0; p < 4; p++) sA[p][tid] = swish_f(acc[p]);
        }
        __syncthreads();

        // L2
        {
            const float4* w = (const float4*)(bW2 + (size_t)tid * 256);
            float bias = bb2[tid];
            float acc[4] = {bias, bias, bias, bias};
            #pragma unroll
            for (int q = 0; q < 64; q += 8) {
                float4 wv[8];
                #pragma unroll
                for (int u = 0; u < 8; u++) wv[u] = w[q + u];
                #pragma unroll
                for (int u = 0; u < 8; u++)
                    #pragma unroll
                    for (int p = 0; p < 4; p++)
                        acc[p] += dot4(wv[u], &sA[p][4 * (q + u)]);
            }
            #pragma unroll
            for (int p = 0; p < 4; p++) sB[p][tid] = swish_f(acc[p]);
        }
        __syncthreads();

        // L3: 256 -> 64, linear
        {
            int r = tid & 63, pg = tid >> 6;
            const float4* w = (const float4*)(bW3 + (size_t)r * 256);
            float acc = bb3[r];
            #pragma unroll
            for (int q = 0; q < 64; q += 8) {
                float4 wv[8];
                #pragma unroll
                for (int u = 0; u < 8; u++) wv[u] = w[q + u];
                #pragma unroll
                for (int u = 0; u < 8; u++)
                    acc += dot4(wv[u], &sB[pg][4 * (q + u)]);
            }
            g_brn[r0 + pg][r] = acc;
        }
    }
}

// ======================= Stage 2: bf16 split pack ==========================
__device__ __forceinline__ void split_store(__nv_bfloat16* row, int z0, float4 u) {
    float uv[4] = {u.x, u.y, u.z, u.w};
    __nv_bfloat16 h[4], lo[4];
    #pragma unroll
    for (int q = 0; q < 4; q++) {
        h[q]  = __float2bfloat16(uv[q]);
        lo[q] = __float2bfloat16(uv[q] - __bfloat162float(h[q]));
    }
    *(__nv_bfloat162*)(row + z0)          = __nv_bfloat162(h[0], h[1]);
    *(__nv_bfloat162*)(row + z0 + 2)      = __nv_bfloat162(h[2], h[3]);
    *(__nv_bfloat162*)(row + 64 + z0)     = __nv_bfloat162(lo[0], lo[1]);
    *(__nv_bfloat162*)(row + 64 + z0 + 2) = __nv_bfloat162(lo[2], lo[3]);
}

__global__ void pack_kernel()
{
    int id = blockIdx.x * 256 + threadIdx.x;
    if (id < 65536) {
        int m = id >> 4, z0 = (id & 15) << 2;
        int i = m >> 6, j = m & 63;
        float4 a = *(const float4*)&g_tn[0][i][z0];
        float4 c = *(const float4*)&g_tn[1][j][z0];
        split_store(g_A + (size_t)m * 128, z0,
                    make_float4(a.x * c.x, a.y * c.y, a.z * c.z, a.w * c.w));
    } else {
        id -= 65536;                       // [0, 262144)
        int n = id >> 4, z0 = (id & 15) << 2;
        int b = n >> 11, k = (n >> 5) & 63, l = n & 31;
        float4 p = *(const float4*)&g_brn[b][z0];
        float4 q = *(const float4*)&g_tn[2][k][z0];
        float4 r = *(const float4*)&g_tn[3][l][z0];
        split_store(g_B + (size_t)n * 128, z0,
                    make_float4(p.x * q.x * r.x, p.y * q.y * r.y,
                                p.z * q.z * r.z, p.w * q.w * r.w));
    }
}

// ======================= Stage 3: mma.sync bf16 GEMM =======================
// CTA tile 128(M) x 128(N), physical K=128 staged once; 3 passes of 4
// k-steps each realize the hi/lo split product.
// smem: A 32KB + B 32KB, XOR-swizzled 16B chunks -> conflict-free ldmatrix.
// 8 warps, 2(M) x 4(N), warp tile 64x32, atoms m16n8k16.
__global__ __launch_bounds__(256, 2)
void gemm_kernel(float* __restrict__ out)
{
    extern __shared__ __align__(128) char smem[];
    char* As = smem;            // [128 rows][256 B]
    char* Bs = smem + 32768;    // [128 rows][256 B]
    const int tid  = threadIdx.x;
    const int wid  = tid >> 5;
    const int lane = tid & 31;
    const int m0 = blockIdx.y * 128;
    const int n0 = blockIdx.x * 128;

    // ---- stage tiles ----
    const __nv_bfloat16* Ag = g_A + (size_t)m0 * 128;
    const __nv_bfloat16* Bg = g_B + (size_t)n0 * 128;
    #pragma unroll
    for (int it = 0; it < 8; it++) {
        int idx = tid + it * 256;        // 0..2047
        int row = idx >> 4;
        int kc  = idx & 15;
        *(uint4*)(As + row * 256 + ((kc ^ (row & 7)) << 4)) =
            *(const uint4*)(Ag + row * 128 + kc * 8);
    }
    #pragma unroll
    for (int it = 0; it < 8; it++) {
        int idx = tid + it * 256;
        int row = idx >> 4;
        int kc  = idx & 15;
        *(uint4*)(Bs + row * 256 + ((kc ^ (row & 7)) << 4)) =
            *(const uint4*)(Bg + row * 128 + kc * 8);
    }
    __syncthreads();

    const int warp_m = wid & 1;          // 0..1  (64 rows each)
    const int warp_n = wid >> 1;         // 0..3  (32 cols each)
    const uint32_t a_base = smem_u32(As);
    const uint32_t b_base = smem_u32(Bs);

    float acc[4][4][4];
    #pragma unroll
    for (int am = 0; am < 4; am++)
        #pragma unroll
        for (int bn = 0; bn < 4; bn++)
            #pragma unroll
            for (int q = 0; q < 4; q++) acc[am][bn][q] = 0.0f;

    // 3 passes: (A hi, B hi), (A lo, B hi), (A hi, B lo)
    #pragma unroll
    for (int pass = 0; pass < 3; pass++) {
        const int a_off = (pass == 1) ? 4 : 0;   // k-step offset (16 elems each)
        const int b_off = (pass == 2) ? 4 : 0;
        #pragma unroll
        for (int ks = 0; ks < 4; ks++) {
            uint32_t a[4][4], b[4][2];
            #pragma unroll
            for (int am = 0; am < 4; am++) {
                int row = warp_m * 64 + am * 16 + (lane & 15);
                int kc  = (a_off + ks) * 2 + (lane >> 4);
                uint32_t addr = a_base + row * 256 + ((kc ^ (row & 7)) << 4);
                asm volatile("ldmatrix.sync.aligned.m8n8.x4.shared.b16 {%0,%1,%2,%3}, [%4];"
                             : "=r"(a[am][0]), "=r"(a[am][1]),
                               "=r"(a[am][2]), "=r"(a[am][3]) : "r"(addr));
            }
            #pragma unroll
            for (int bn = 0; bn < 4; bn++) {
                int row = warp_n * 32 + bn * 8 + (lane & 7);
                int kc  = (b_off + ks) * 2 + ((lane >> 3) & 1);
                uint32_t addr = b_base + row * 256 + ((kc ^ (row & 7)) << 4);
                asm volatile("ldmatrix.sync.aligned.m8n8.x2.shared.b16 {%0,%1}, [%2];"
                             : "=r"(b[bn][0]), "=r"(b[bn][1]) : "r"(addr));
            }
            #pragma unroll
            for (int am = 0; am < 4; am++)
                #pragma unroll
                for (int bn = 0; bn < 4; bn++)
                    asm volatile(
                        "mma.sync.aligned.m16n8k16.row.col.f32.bf16.bf16.f32 "
                        "{%0,%1,%2,%3}, {%4,%5,%6,%7}, {%8,%9}, {%0,%1,%2,%3};"
                        : "+f"(acc[am][bn][0]), "+f"(acc[am][bn][1]),
                          "+f"(acc[am][bn][2]), "+f"(acc[am][bn][3])
                        : "r"(a[am][0]), "r"(a[am][1]), "r"(a[am][2]), "r"(a[am][3]),
                          "r"(b[bn][0]), "r"(b[bn][1]));
        }
    }

    // ---- epilogue: out[(((b*64+i)*64+j)*64+k)*32+l] ----
    #pragma unroll
    for (int am = 0; am < 4; am++) {
        #pragma unroll
        for (int bn = 0; bn < 4; bn++) {
            int mg = m0 + warp_m * 64 + am * 16 + (lane >> 2);
            int ng = n0 + warp_n * 32 + bn * 8 + (lane & 3) * 2;
            int bi = ng >> 11, rem = ng & 2047;
            {
                int i = mg >> 6, j = mg & 63;
                float* p = out + (((size_t)bi * 64 + i) * 64 + j) * 2048 + rem;
                *(float2*)p = make_float2(acc[am][bn][0], acc[am][bn][1]);
            }
            {
                int mg2 = mg + 8;
                int i = mg2 >> 6, j = mg2 & 63;
                float* p = out + (((size_t)bi * 64 + i) * 64 + j) * 2048 + rem;
                *(float2*)p = make_float2(acc[am][bn][2], acc[am][bn][3]);
            }
        }
    }
}

// ======================= launch ============================================
extern "C" void kernel_launch(void* const* d_in, const int* in_sizes, int n_in,
                              void* d_out, int out_size)
{
    const float* x1  = (const float*)d_in[0];
    const float* x2  = (const float*)d_in[1];
    const float* x3  = (const float*)d_in[2];
    const float* x4  = (const float*)d_in[3];
    const float* f   = (const float*)d_in[4];
    const float* Bm  = (const float*)d_in[5];
    const float* tW0 = (const float*)d_in[6];
    const float* tb0 = (const float*)d_in[7];
    const float* tW1 = (const float*)d_in[8];
    const float* tb1 = (const float*)d_in[9];
    const float* tW2 = (const float*)d_in[10];
    const float* tb2 = (const float*)d_in[11];
    const float* tW3 = (const float*)d_in[12];
    const float* tb3 = (const float*)d_in[13];
    const float* bW0 = (const float*)d_in[14];
    const float* bb0 = (const float*)d_in[15];
    const float* bW1 = (const float*)d_in[16];
    const float* bb1 = (const float*)d_in[17];
    const float* bW2 = (const float*)d_in[18];
    const float* bb2 = (const float*)d_in[19];
    const float* bW3 = (const float*)d_in[20];
    const float* bb3 = (const float*)d_in[21];

    mlp_kernel<<<58, 256>>>(x1, x2, x3, x4, f, Bm,
                            tW0, tb0, tW1, tb1, tW2, tb2, tW3, tb3,
                            bW0, bb0, bW1, bb1, bW2, bb2, bW3, bb3);

    pack_kernel<<<1280, 256>>>();

    cudaFuncSetAttribute(gemm_kernel,
                         cudaFuncAttributeMaxDynamicSharedMemorySize, 65536);
    dim3 grid(128, 32);
    gemm_kernel<<<grid, 256, 65536>>>((float*)d_out);
}

// round 7
// speedup vs baseline: 2.1071x; 1.2422x over previous
#include <cuda_runtime.h>
#include <cuda_bf16.h>
#include <math.h>
#include <stdint.h>

// ---------------------------------------------------------------------------
// DeepOHeat_ST: 4 trunk MLPs + branch MLP -> rank-64 CP outer product.
//
// Stage 1 (mlp_kernel): batched-point MLPs with smem-staged weights
//   (coalesced LDG; fixes L1tex wavefront serialization of row-per-thread).
// Stage 2 (pack_kernel): bf16 hi/lo split operands  A'=[uh|ul], B'=[wh|wl]
// Stage 3 (gemm_kernel): out = u @ w^T via mma.sync bf16, fp32 accum,
//     3-pass split:  uh*wh + ul*wh + uh*wl   (residual ul*wl ~ 2^-16)
// ---------------------------------------------------------------------------

#define H 256
#define R 64
#define NF 64
#define WSTRIDE 68   // padded smem row stride (floats), 16B aligned, low conflict

__device__ float g_tn[4][64][64];            // [trunk][point][z]
__device__ float g_brn[8][64];               // [batch][z]
__device__ __nv_bfloat16 g_A[4096 * 128];    // [m][k]  k: 0..63 hi, 64..127 lo
__device__ __nv_bfloat16 g_B[16384 * 128];   // [n][k]

__device__ __forceinline__ float swish_f(float v) {
    return v / (1.0f + __expf(-v));
}
__device__ __forceinline__ uint32_t smem_u32(const void* p) {
    uint32_t a;
    asm("{ .reg .u64 t; cvta.to.shared.u64 t, %1; cvt.u32.u64 %0, t; }"
        : "=r"(a) : "l"(p));
    return a;
}

// One 256-wide hidden layer over 4 points, weights staged through smem.
// actIn/actOut are distinct buffers. Wt is the 256xWSTRIDE staging area.
__device__ __forceinline__ void layer256(
    const float* __restrict__ W, float bias, int in_dim,
    const float (*actIn)[256], float (*actOut)[256],
    float* Wt, int tid, bool do_swish)
{
    float acc[4] = {bias, bias, bias, bias};
    for (int k0 = 0; k0 < in_dim; k0 += 64) {
        __syncthreads();               // Wt free from previous use
        #pragma unroll
        for (int s = 0; s < 16; s++) { // stage 256 rows x 64 k, coalesced
            int idx = tid + s * 256;
            int row = idx >> 4, kc = idx & 15;
            *(float4*)&Wt[row * WSTRIDE + kc * 4] =
                *(const float4*)&W[(size_t)row * in_dim + k0 + kc * 4];
        }
        __syncthreads();
        #pragma unroll
        for (int kc = 0; kc < 16; kc++) {
            float4 w = *(const float4*)&Wt[tid * WSTRIDE + kc * 4];
            #pragma unroll
            for (int p = 0; p < 4; p++) {
                const float* a = &actIn[p][k0 + kc * 4];
                acc[p] += w.x * a[0] + w.y * a[1] + w.z * a[2] + w.w * a[3];
            }
        }
    }
    #pragma unroll
    for (int p = 0; p < 4; p++)
        actOut[p][tid] = do_swish ? swish_f(acc[p]) : acc[p];
}

// Final layer: 256 -> 64, linear; tid = (pg = tid>>6, r = tid&63).
__device__ __forceinline__ float layer_out(
    const float* __restrict__ W, const float* __restrict__ bias,
    const float (*actIn)[256], float* Wt, int tid)
{
    const int r = tid & 63, pg = tid >> 6;
    float acc = bias[r];
    for (int k0 = 0; k0 < 256; k0 += 64) {
        __syncthreads();
        #pragma unroll
        for (int s = 0; s < 4; s++) {  // stage 64 rows x 64 k
            int idx = tid + s * 256;
            int row = idx >> 4, kc = idx & 15;
            *(float4*)&Wt[row * WSTRIDE + kc * 4] =
                *(const float4*)&W[(size_t)row * 256 + k0 + kc * 4];
        }
        __syncthreads();
        #pragma unroll
        for (int kc = 0; kc < 16; kc++) {
            float4 w = *(const float4*)&Wt[r * WSTRIDE + kc * 4];
            const float* a = &actIn[pg][k0 + kc * 4];
            acc += w.x * a[0] + w.y * a[1] + w.z * a[2] + w.w * a[3];
        }
    }
    return acc;
}

// ======================= Stage 1: batched MLPs =============================
// Blocks 0..47: trunks 0..2 (16 each, 4 points); 48..55: trunk 3; 56..57: branch.
__global__ __launch_bounds__(256, 2)
void mlp_kernel(
    const float* __restrict__ x1, const float* __restrict__ x2,
    const float* __restrict__ x3, const float* __restrict__ x4,
    const float* __restrict__ f,  const float* __restrict__ Bmat,
    const float* __restrict__ tW0, const float* __restrict__ tb0,
    const float* __restrict__ tW1, const float* __restrict__ tb1,
    const float* __restrict__ tW2, const float* __restrict__ tb2,
    const float* __restrict__ tW3, const float* __restrict__ tb3,
    const float* __restrict__ bW0, const float* __restrict__ bb0,
    const float* __restrict__ bW1, const float* __restrict__ bb1,
    const float* __restrict__ bW2, const float* __restrict__ bb2,
    const float* __restrict__ bW3, const float* __restrict__ bb3)
{
    extern __shared__ float smem[];
    float* Wt = smem;                                    // [256][WSTRIDE]
    float (*actA)[256] = (float (*)[256])(smem + 256 * WSTRIDE);
    float (*actB)[256] = actA + 4;
    const int bid = blockIdx.x;
    const int tid = threadIdx.x;

    if (bid < 56) {
        // ---------------- trunk path: 4 points ----------------
        int d, n0;
        if (bid < 48) { d = bid >> 4; n0 = (bid & 15) << 2; }
        else          { d = 3;        n0 = (bid - 48) << 2; }
        const float* xp = (d == 0) ? x1 : (d == 1) ? x2 : (d == 2) ? x3 : x4;

        // Fourier features: actA[p][0:128]
        #pragma unroll
        for (int it = 0; it < 2; it++) {
            int idx = tid + it * 256;        // 0..511
            int p = idx >> 7, ff = idx & 127;
            float x = xp[n0 + p];
            actA[p][ff] = (ff < 64) ? cosf(x * Bmat[ff]) : sinf(x * Bmat[ff - 64]);
        }

        layer256(tW0 + (size_t)d * H * 128, tb0[d * H + tid], 128,
                 actA, actB, Wt, tid, true);
        layer256(tW1 + (size_t)d * H * 256, tb1[d * H + tid], 256,
                 actB, actA, Wt, tid, true);
        layer256(tW2 + (size_t)d * H * 256, tb2[d * H + tid], 256,
                 actA, actB, Wt, tid, true);
        float v = layer_out(tW3 + (size_t)d * R * 256, tb3 + d * R,
                            actB, Wt, tid);
        g_tn[d][n0 + (tid >> 6)][tid & 63] = v;
    } else {
        // ---------------- branch path: 4 rows ----------------
        const int r0 = (bid - 56) << 2;
        #pragma unroll
        for (int it = 0; it < 4; it++) {
            int idx = tid + it * 256;        // 0..1023
            int p = idx >> 8, ff = idx & 255;
            actA[p][ff] = f[(r0 + p) * 256 + ff];
        }

        layer256(bW0, bb0[tid], 256, actA, actB, Wt, tid, true);
        layer256(bW1, bb1[tid], 256, actB, actA, Wt, tid, true);
        layer256(bW2, bb2[tid], 256, actA, actB, Wt, tid, true);
        float v = layer_out(bW3, bb3, actB, Wt, tid);
        g_brn[r0 + (tid >> 6)][tid & 63] = v;
    }
}

// ======================= Stage 2: bf16 split pack ==========================
__device__ __forceinline__ void split_store(__nv_bfloat16* row, int z0, float4 u) {
    float uv[4] = {u.x, u.y, u.z, u.w};
    __nv_bfloat16 h[4], lo[4];
    #pragma unroll
    for (int q = 0; q < 4; q++) {
        h[q]  = __float2bfloat16(uv[q]);
        lo[q] = __float2bfloat16(uv[q] - __bfloat162float(h[q]));
    }
    *(__nv_bfloat162*)(row + z0)          = __nv_bfloat162(h[0], h[1]);
    *(__nv_bfloat162*)(row + z0 + 2)      = __nv_bfloat162(h[2], h[3]);
    *(__nv_bfloat162*)(row + 64 + z0)     = __nv_bfloat162(lo[0], lo[1]);
    *(__nv_bfloat162*)(row + 64 + z0 + 2) = __nv_bfloat162(lo[2], lo[3]);
}

__global__ void pack_kernel()
{
    int id = blockIdx.x * 256 + threadIdx.x;
    if (id < 65536) {
        int m = id >> 4, z0 = (id & 15) << 2;
        int i = m >> 6, j = m & 63;
        float4 a = *(const float4*)&g_tn[0][i][z0];
        float4 c = *(const float4*)&g_tn[1][j][z0];
        split_store(g_A + (size_t)m * 128, z0,
                    make_float4(a.x * c.x, a.y * c.y, a.z * c.z, a.w * c.w));
    } else {
        id -= 65536;                       // [0, 262144)
        int n = id >> 4, z0 = (id & 15) << 2;
        int b = n >> 11, k = (n >> 5) & 63, l = n & 31;
        float4 p = *(const float4*)&g_brn[b][z0];
        float4 q = *(const float4*)&g_tn[2][k][z0];
        float4 r = *(const float4*)&g_tn[3][l][z0];
        split_store(g_B + (size_t)n * 128, z0,
                    make_float4(p.x * q.x * r.x, p.y * q.y * r.y,
                                p.z * q.z * r.z, p.w * q.w * r.w));
    }
}

// ======================= Stage 3: mma.sync bf16 GEMM =======================
// CTA tile 128(M) x 128(N), physical K=128 staged once; 3 passes of 4
// k-steps each realize the hi/lo split product.
// smem: A 32KB + B 32KB, XOR-swizzled 16B chunks -> conflict-free ldmatrix.
// 8 warps, 2(M) x 4(N), warp tile 64x32, atoms m16n8k16.
__global__ __launch_bounds__(256, 2)
void gemm_kernel(float* __restrict__ out)
{
    extern __shared__ __align__(128) char gsm[];
    char* As = gsm;            // [128 rows][256 B]
    char* Bs = gsm + 32768;    // [128 rows][256 B]
    const int tid  = threadIdx.x;
    const int wid  = tid >> 5;
    const int lane = tid & 31;
    const int m0 = blockIdx.y * 128;
    const int n0 = blockIdx.x * 128;

    // ---- stage tiles ----
    const __nv_bfloat16* Ag = g_A + (size_t)m0 * 128;
    const __nv_bfloat16* Bg = g_B + (size_t)n0 * 128;
    #pragma unroll
    for (int it = 0; it < 8; it++) {
        int idx = tid + it * 256;        // 0..2047
        int row = idx >> 4;
        int kc  = idx & 15;
        *(uint4*)(As + row * 256 + ((kc ^ (row & 7)) << 4)) =
            *(const uint4*)(Ag + row * 128 + kc * 8);
    }
    #pragma unroll
    for (int it = 0; it < 8; it++) {
        int idx = tid + it * 256;
        int row = idx >> 4;
        int kc  = idx & 15;
        *(uint4*)(Bs + row * 256 + ((kc ^ (row & 7)) << 4)) =
            *(const uint4*)(Bg + row * 128 + kc * 8);
    }
    __syncthreads();

    const int warp_m = wid & 1;          // 0..1  (64 rows each)
    const int warp_n = wid >> 1;         // 0..3  (32 cols each)
    const uint32_t a_base = smem_u32(As);
    const uint32_t b_base = smem_u32(Bs);

    float acc[4][4][4];
    #pragma unroll
    for (int am = 0; am < 4; am++)
        #pragma unroll
        for (int bn = 0; bn < 4; bn++)
            #pragma unroll
            for (int q = 0; q < 4; q++) acc[am][bn][q] = 0.0f;

    // 3 passes: (A hi, B hi), (A lo, B hi), (A hi, B lo)
    #pragma unroll
    for (int pass = 0; pass < 3; pass++) {
        const int a_off = (pass == 1) ? 4 : 0;   // k-step offset (16 elems each)
        const int b_off = (pass == 2) ? 4 : 0;
        #pragma unroll
        for (int ks = 0; ks < 4; ks++) {
            uint32_t a[4][4], b[4][2];
            #pragma unroll
            for (int am = 0; am < 4; am++) {
                int row = warp_m * 64 + am * 16 + (lane & 15);
                int kc  = (a_off + ks) * 2 + (lane >> 4);
                uint32_t addr = a_base + row * 256 + ((kc ^ (row & 7)) << 4);
                asm volatile("ldmatrix.sync.aligned.m8n8.x4.shared.b16 {%0,%1,%2,%3}, [%4];"
                             : "=r"(a[am][0]), "=r"(a[am][1]),
                               "=r"(a[am][2]), "=r"(a[am][3]) : "r"(addr));
            }
            #pragma unroll
            for (int bn = 0; bn < 4; bn++) {
                int row = warp_n * 32 + bn * 8 + (lane & 7);
                int kc  = (b_off + ks) * 2 + ((lane >> 3) & 1);
                uint32_t addr = b_base + row * 256 + ((kc ^ (row & 7)) << 4);
                asm volatile("ldmatrix.sync.aligned.m8n8.x2.shared.b16 {%0,%1}, [%2];"
                             : "=r"(b[bn][0]), "=r"(b[bn][1]) : "r"(addr));
            }
            #pragma unroll
            for (int am = 0; am < 4; am++)
                #pragma unroll
                for (int bn = 0; bn < 4; bn++)
                    asm volatile(
                        "mma.sync.aligned.m16n8k16.row.col.f32.bf16.bf16.f32 "
                        "{%0,%1,%2,%3}, {%4,%5,%6,%7}, {%8,%9}, {%0,%1,%2,%3};"
                        : "+f"(acc[am][bn][0]), "+f"(acc[am][bn][1]),
                          "+f"(acc[am][bn][2]), "+f"(acc[am][bn][3])
                        : "r"(a[am][0]), "r"(a[am][1]), "r"(a[am][2]), "r"(a[am][3]),
                          "r"(b[bn][0]), "r"(b[bn][1]));
        }
    }

    // ---- epilogue: out[(((b*64+i)*64+j)*64+k)*32+l] ----
    #pragma unroll
    for (int am = 0; am < 4; am++) {
        #pragma unroll
        for (int bn = 0; bn < 4; bn++) {
            int mg = m0 + warp_m * 64 + am * 16 + (lane >> 2);
            int ng = n0 + warp_n * 32 + bn * 8 + (lane & 3) * 2;
            int bi = ng >> 11, rem = ng & 2047;
            {
                int i = mg >> 6, j = mg & 63;
                float* p = out + (((size_t)bi * 64 + i) * 64 + j) * 2048 + rem;
                *(float2*)p = make_float2(acc[am][bn][0], acc[am][bn][1]);
            }
            {
                int mg2 = mg + 8;
                int i = mg2 >> 6, j = mg2 & 63;
                float* p = out + (((size_t)bi * 64 + i) * 64 + j) * 2048 + rem;
                *(float2*)p = make_float2(acc[am][bn][2], acc[am][bn][3]);
            }
        }
    }
}

// ======================= launch ============================================
#define MLP_SMEM (256 * WSTRIDE * 4 + 2 * 4 * 256 * 4)

extern "C" void kernel_launch(void* const* d_in, const int* in_sizes, int n_in,
                              void* d_out, int out_size)
{
    const float* x1  = (const float*)d_in[0];
    const float* x2  = (const float*)d_in[1];
    const float* x3  = (const float*)d_in[2];
    const float* x4  = (const float*)d_in[3];
    const float* f   = (const float*)d_in[4];
    const float* Bm  = (const float*)d_in[5];
    const float* tW0 = (const float*)d_in[6];
    const float* tb0 = (const float*)d_in[7];
    const float* tW1 = (const float*)d_in[8];
    const float* tb1 = (const float*)d_in[9];
    const float* tW2 = (const float*)d_in[10];
    const float* tb2 = (const float*)d_in[11];
    const float* tW3 = (const float*)d_in[12];
    const float* tb3 = (const float*)d_in[13];
    const float* bW0 = (const float*)d_in[14];
    const float* bb0 = (const float*)d_in[15];
    const float* bW1 = (const float*)d_in[16];
    const float* bb1 = (const float*)d_in[17];
    const float* bW2 = (const float*)d_in[18];
    const float* bb2 = (const float*)d_in[19];
    const float* bW3 = (const float*)d_in[20];
    const float* bb3 = (const float*)d_in[21];

    cudaFuncSetAttribute(mlp_kernel,
                         cudaFuncAttributeMaxDynamicSharedMemorySize, MLP_SMEM);
    mlp_kernel<<<58, 256, MLP_SMEM>>>(x1, x2, x3, x4, f, Bm,
                                      tW0, tb0, tW1, tb1, tW2, tb2, tW3, tb3,
                                      bW0, bb0, bW1, bb1, bW2, bb2, bW3, bb3);

    pack_kernel<<<1280, 256>>>();

    cudaFuncSetAttribute(gemm_kernel,
                         cudaFuncAttributeMaxDynamicSharedMemorySize, 65536);
    dim3 grid(128, 32);
    gemm_kernel<<<grid, 256, 65536>>>((float*)d_out);
}

// round 8
// speedup vs baseline: 2.1846x; 1.0368x over previous
#include <cuda_runtime.h>
#include <cuda_bf16.h>
#include <math.h>
#include <stdint.h>

// ---------------------------------------------------------------------------
// DeepOHeat_ST: 4 trunk MLPs + branch MLP -> rank-64 CP outer product.
//
// Stage 1 (mlp_kernel): batched-point MLPs; weights staged via double-
//   buffered cp.async 32-col chunks (latency hidden behind compute).
// Stage 2 (pack_kernel): bf16 hi/lo split operands  A'=[uh|ul], B'=[wh|wl]
// Stage 3 (gemm_kernel): out = u @ w^T via mma.sync bf16, fp32 accum,
//     3-pass split:  uh*wh + ul*wh + uh*wl   (residual ul*wl ~ 2^-16)
// ---------------------------------------------------------------------------

#define H 256
#define R 64
#define NF 64
#define WST 36   // smem weight row stride in floats (32 data + 4 pad)

__device__ float g_tn[4][64][64];            // [trunk][point][z]
__device__ float g_brn[8][64];               // [batch][z]
__device__ __nv_bfloat16 g_A[4096 * 128];    // [m][k]  k: 0..63 hi, 64..127 lo
__device__ __nv_bfloat16 g_B[16384 * 128];   // [n][k]

__device__ __forceinline__ float swish_f(float v) {
    return v / (1.0f + __expf(-v));
}
__device__ __forceinline__ uint32_t smem_u32(const void* p) {
    uint32_t a;
    asm("{ .reg .u64 t; cvta.to.shared.u64 t, %1; cvt.u32.u64 %0, t; }"
        : "=r"(a) : "l"(p));
    return a;
}

#define CP_ASYNC16(dst_u32, src_ptr) \
    asm volatile("cp.async.cg.shared.global [%0], [%1], 16;" \
                 :: "r"(dst_u32), "l"(src_ptr))
#define CP_COMMIT()  asm volatile("cp.async.commit_group;")
#define CP_WAIT0()   asm volatile("cp.async.wait_group 0;")
#define CP_WAIT1()   asm volatile("cp.async.wait_group 1;")

// stage a 256-row x 32-col weight chunk into smem (8 float4 per thread)
__device__ __forceinline__ void stage256(
    uint32_t wt, const float* __restrict__ W, int in_dim, int k0, int tid)
{
    #pragma unroll
    for (int s = 0; s < 8; s++) {
        int idx = tid + s * 256;
        int row = idx >> 3, kc = idx & 7;
        CP_ASYNC16(wt + (uint32_t)(row * WST + kc * 4) * 4,
                   W + (size_t)row * in_dim + k0 + kc * 4);
    }
    CP_COMMIT();
}
// stage a 64-row x 32-col chunk (2 float4 per thread)
__device__ __forceinline__ void stage64(
    uint32_t wt, const float* __restrict__ W, int k0, int tid)
{
    #pragma unroll
    for (int s = 0; s < 2; s++) {
        int idx = tid + s * 256;
        int row = idx >> 3, kc = idx & 7;
        CP_ASYNC16(wt + (uint32_t)(row * WST + kc * 4) * 4,
                   W + (size_t)row * 256 + k0 + kc * 4);
    }
    CP_COMMIT();
}

// One 256-wide layer over 4 points; cp.async double-buffered weights.
__device__ __forceinline__ void layer256(
    const float* __restrict__ W, float bias, int in_dim,
    const float (*actIn)[256], float (*actOut)[256],
    float* wtp0, float* wtp1, uint32_t wta0, uint32_t wta1,
    int tid, bool do_swish)
{
    const int nc = in_dim >> 5;
    stage256(wta0, W, in_dim, 0, tid);
    stage256(wta1, W, in_dim, 32, tid);
    float acc[4] = {bias, bias, bias, bias};
    for (int c = 0; c < nc; c++) {
        if (c == nc - 1) { CP_WAIT0(); } else { CP_WAIT1(); }
        __syncthreads();
        const float* wtp = (c & 1) ? wtp1 : wtp0;
        #pragma unroll
        for (int kc = 0; kc < 8; kc++) {
            float4 w = *(const float4*)&wtp[tid * WST + kc * 4];
            #pragma unroll
            for (int p = 0; p < 4; p++) {
                const float* a = &actIn[p][c * 32 + kc * 4];
                acc[p] += w.x * a[0] + w.y * a[1] + w.z * a[2] + w.w * a[3];
            }
        }
        __syncthreads();
        if (c + 2 < nc)
            stage256((c & 1) ? wta1 : wta0, W, in_dim, (c + 2) * 32, tid);
    }
    #pragma unroll
    for (int p = 0; p < 4; p++)
        actOut[p][tid] = do_swish ? swish_f(acc[p]) : acc[p];
}

// Final layer: 256 -> 64, linear; tid = (pg = tid>>6, r = tid&63).
__device__ __forceinline__ float layer_out(
    const float* __restrict__ W, const float* __restrict__ bias,
    const float (*actIn)[256],
    float* wtp0, float* wtp1, uint32_t wta0, uint32_t wta1, int tid)
{
    const int r = tid & 63, pg = tid >> 6;
    stage64(wta0, W, 0, tid);
    stage64(wta1, W, 32, tid);
    float acc = bias[r];
    #pragma unroll
    for (int c = 0; c < 8; c++) {
        if (c == 7) { CP_WAIT0(); } else { CP_WAIT1(); }
        __syncthreads();
        const float* wtp = (c & 1) ? wtp1 : wtp0;
        #pragma unroll
        for (int kc = 0; kc < 8; kc++) {
            float4 w = *(const float4*)&wtp[r * WST + kc * 4];
            const float* a = &actIn[pg][c * 32 + kc * 4];
            acc += w.x * a[0] + w.y * a[1] + w.z * a[2] + w.w * a[3];
        }
        __syncthreads();
        if (c + 2 < 8)
            stage64((c & 1) ? wta1 : wta0, W, (c + 2) * 32, tid);
    }
    return acc;
}

// ======================= Stage 1: batched MLPs =============================
// Blocks 0..47: trunks 0..2 (16 each, 4 points); 48..55: trunk 3; 56..57: branch.
__global__ __launch_bounds__(256, 1)
void mlp_kernel(
    const float* __restrict__ x1, const float* __restrict__ x2,
    const float* __restrict__ x3, const float* __restrict__ x4,
    const float* __restrict__ f,  const float* __restrict__ Bmat,
    const float* __restrict__ tW0, const float* __restrict__ tb0,
    const float* __restrict__ tW1, const float* __restrict__ tb1,
    const float* __restrict__ tW2, const float* __restrict__ tb2,
    const float* __restrict__ tW3, const float* __restrict__ tb3,
    const float* __restrict__ bW0, const float* __restrict__ bb0,
    const float* __restrict__ bW1, const float* __restrict__ bb1,
    const float* __restrict__ bW2, const float* __restrict__ bb2,
    const float* __restrict__ bW3, const float* __restrict__ bb3)
{
    extern __shared__ float smem[];
    float* wtp0 = smem;                      // [256][WST]
    float* wtp1 = smem + 256 * WST;
    float (*actA)[256] = (float (*)[256])(smem + 2 * 256 * WST);
    float (*actB)[256] = actA + 4;
    const uint32_t wta0 = smem_u32(wtp0);
    const uint32_t wta1 = smem_u32(wtp1);
    const int bid = blockIdx.x;
    const int tid = threadIdx.x;

    if (bid < 56) {
        // ---------------- trunk path: 4 points ----------------
        int d, n0;
        if (bid < 48) { d = bid >> 4; n0 = (bid & 15) << 2; }
        else          { d = 3;        n0 = (bid - 48) << 2; }
        const float* xp = (d == 0) ? x1 : (d == 1) ? x2 : (d == 2) ? x3 : x4;

        #pragma unroll
        for (int it = 0; it < 2; it++) {
            int idx = tid + it * 256;        // 0..511
            int p = idx >> 7, ff = idx & 127;
            float x = xp[n0 + p];
            actA[p][ff] = (ff < 64) ? cosf(x * Bmat[ff]) : sinf(x * Bmat[ff - 64]);
        }
        __syncthreads();

        layer256(tW0 + (size_t)d * H * 128, tb0[d * H + tid], 128,
                 actA, actB, wtp0, wtp1, wta0, wta1, tid, true);
        layer256(tW1 + (size_t)d * H * 256, tb1[d * H + tid], 256,
                 actB, actA, wtp0, wtp1, wta0, wta1, tid, true);
        layer256(tW2 + (size_t)d * H * 256, tb2[d * H + tid], 256,
                 actA, actB, wtp0, wtp1, wta0, wta1, tid, true);
        float v = layer_out(tW3 + (size_t)d * R * 256, tb3 + d * R,
                            actB, wtp0, wtp1, wta0, wta1, tid);
        g_tn[d][n0 + (tid >> 6)][tid & 63] = v;
    } else {
        // ---------------- branch path: 4 rows ----------------
        const int r0 = (bid - 56) << 2;
        #pragma unroll
        for (int it = 0; it < 4; it++) {
            int idx = tid + it * 256;        // 0..1023
            int p = idx >> 8, ff = idx & 255;
            actA[p][ff] = f[(r0 + p) * 256 + ff];
        }
        __syncthreads();

        layer256(bW0, bb0[tid], 256, actA, actB, wtp0, wtp1, wta0, wta1, tid, true);
        layer256(bW1, bb1[tid], 256, actB, actA, wtp0, wtp1, wta0, wta1, tid, true);
        layer256(bW2, bb2[tid], 256, actA, actB, wtp0, wtp1, wta0, wta1, tid, true);
        float v = layer_out(bW3, bb3, actB, wtp0, wtp1, wta0, wta1, tid);
        g_brn[r0 + (tid >> 6)][tid & 63] = v;
    }
}

// ======================= Stage 2: bf16 split pack ==========================
__device__ __forceinline__ void split_store(__nv_bfloat16* row, int z0, float4 u) {
    float uv[4] = {u.x, u.y, u.z, u.w};
    __nv_bfloat16 h[4], lo[4];
    #pragma unroll
    for (int q = 0; q < 4; q++) {
        h[q]  = __float2bfloat16(uv[q]);
        lo[q] = __float2bfloat16(uv[q] - __bfloat162float(h[q]));
    }
    *(__nv_bfloat162*)(row + z0)          = __nv_bfloat162(h[0], h[1]);
    *(__nv_bfloat162*)(row + z0 + 2)      = __nv_bfloat162(h[2], h[3]);
    *(__nv_bfloat162*)(row + 64 + z0)     = __nv_bfloat162(lo[0], lo[1]);
    *(__nv_bfloat162*)(row + 64 + z0 + 2) = __nv_bfloat162(lo[2], lo[3]);
}

__global__ void pack_kernel()
{
    int id = blockIdx.x * 256 + threadIdx.x;
    if (id < 65536) {
        int m = id >> 4, z0 = (id & 15) << 2;
        int i = m >> 6, j = m & 63;
        float4 a = *(const float4*)&g_tn[0][i][z0];
        float4 c = *(const float4*)&g_tn[1][j][z0];
        split_store(g_A + (size_t)m * 128, z0,
                    make_float4(a.x * c.x, a.y * c.y, a.z * c.z, a.w * c.w));
    } else {
        id -= 65536;                       // [0, 262144)
        int n = id >> 4, z0 = (id & 15) << 2;
        int b = n >> 11, k = (n >> 5) & 63, l = n & 31;
        float4 p = *(const float4*)&g_brn[b][z0];
        float4 q = *(const float4*)&g_tn[2][k][z0];
        float4 r = *(const float4*)&g_tn[3][l][z0];
        split_store(g_B + (size_t)n * 128, z0,
                    make_float4(p.x * q.x * r.x, p.y * q.y * r.y,
                                p.z * q.z * r.z, p.w * q.w * r.w));
    }
}

// ======================= Stage 3: mma.sync bf16 GEMM =======================
// CTA tile 128(M) x 128(N), physical K=128 staged once; 3 passes of 4
// k-steps each realize the hi/lo split product.
// smem: A 32KB + B 32KB, XOR-swizzled 16B chunks -> conflict-free ldmatrix.
// 8 warps, 2(M) x 4(N), warp tile 64x32, atoms m16n8k16.
__global__ __launch_bounds__(256, 2)
void gemm_kernel(float* __restrict__ out)
{
    extern __shared__ __align__(128) char gsm[];
    char* As = gsm;            // [128 rows][256 B]
    char* Bs = gsm + 32768;    // [128 rows][256 B]
    const int tid  = threadIdx.x;
    const int wid  = tid >> 5;
    const int lane = tid & 31;
    const int m0 = blockIdx.y * 128;
    const int n0 = blockIdx.x * 128;

    // ---- stage tiles ----
    const __nv_bfloat16* Ag = g_A + (size_t)m0 * 128;
    const __nv_bfloat16* Bg = g_B + (size_t)n0 * 128;
    #pragma unroll
    for (int it = 0; it < 8; it++) {
        int idx = tid + it * 256;        // 0..2047
        int row = idx >> 4;
        int kc  = idx & 15;
        *(uint4*)(As + row * 256 + ((kc ^ (row & 7)) << 4)) =
            *(const uint4*)(Ag + row * 128 + kc * 8);
    }
    #pragma unroll
    for (int it = 0; it < 8; it++) {
        int idx = tid + it * 256;
        int row = idx >> 4;
        int kc  = idx & 15;
        *(uint4*)(Bs + row * 256 + ((kc ^ (row & 7)) << 4)) =
            *(const uint4*)(Bg + row * 128 + kc * 8);
    }
    __syncthreads();

    const int warp_m = wid & 1;          // 0..1  (64 rows each)
    const int warp_n = wid >> 1;         // 0..3  (32 cols each)
    const uint32_t a_base = smem_u32(As);
    const uint32_t b_base = smem_u32(Bs);

    float acc[4][4][4];
    #pragma unroll
    for (int am = 0; am < 4; am++)
        #pragma unroll
        for (int bn = 0; bn < 4; bn++)
            #pragma unroll
            for (int q = 0; q < 4; q++) acc[am][bn][q] = 0.0f;

    // 3 passes: (A hi, B hi), (A lo, B hi), (A hi, B lo)
    #pragma unroll
    for (int pass = 0; pass < 3; pass++) {
        const int a_off = (pass == 1) ? 4 : 0;   // k-step offset (16 elems each)
        const int b_off = (pass == 2) ? 4 : 0;
        #pragma unroll
        for (int ks = 0; ks < 4; ks++) {
            uint32_t a[4][4], b[4][2];
            #pragma unroll
            for (int am = 0; am < 4; am++) {
                int row = warp_m * 64 + am * 16 + (lane & 15);
                int kc  = (a_off + ks) * 2 + (lane >> 4);
                uint32_t addr = a_base + row * 256 + ((kc ^ (row & 7)) << 4);
                asm volatile("ldmatrix.sync.aligned.m8n8.x4.shared.b16 {%0,%1,%2,%3}, [%4];"
                             : "=r"(a[am][0]), "=r"(a[am][1]),
                               "=r"(a[am][2]), "=r"(a[am][3]) : "r"(addr));
            }
            #pragma unroll
            for (int bn = 0; bn < 4; bn++) {
                int row = warp_n * 32 + bn * 8 + (lane & 7);
                int kc  = (b_off + ks) * 2 + ((lane >> 3) & 1);
                uint32_t addr = b_base + row * 256 + ((kc ^ (row & 7)) << 4);
                asm volatile("ldmatrix.sync.aligned.m8n8.x2.shared.b16 {%0,%1}, [%2];"
                             : "=r"(b[bn][0]), "=r"(b[bn][1]) : "r"(addr));
            }
            #pragma unroll
            for (int am = 0; am < 4; am++)
                #pragma unroll
                for (int bn = 0; bn < 4; bn++)
                    asm volatile(
                        "mma.sync.aligned.m16n8k16.row.col.f32.bf16.bf16.f32 "
                        "{%0,%1,%2,%3}, {%4,%5,%6,%7}, {%8,%9}, {%0,%1,%2,%3};"
                        : "+f"(acc[am][bn][0]), "+f"(acc[am][bn][1]),
                          "+f"(acc[am][bn][2]), "+f"(acc[am][bn][3])
                        : "r"(a[am][0]), "r"(a[am][1]), "r"(a[am][2]), "r"(a[am][3]),
                          "r"(b[bn][0]), "r"(b[bn][1]));
        }
    }

    // ---- epilogue: out[(((b*64+i)*64+j)*64+k)*32+l] ----
    #pragma unroll
    for (int am = 0; am < 4; am++) {
        #pragma unroll
        for (int bn = 0; bn < 4; bn++) {
            int mg = m0 + warp_m * 64 + am * 16 + (lane >> 2);
            int ng = n0 + warp_n * 32 + bn * 8 + (lane & 3) * 2;
            int bi = ng >> 11, rem = ng & 2047;
            {
                int i = mg >> 6, j = mg & 63;
                float* p = out + (((size_t)bi * 64 + i) * 64 + j) * 2048 + rem;
                *(float2*)p = make_float2(acc[am][bn][0], acc[am][bn][1]);
            }
            {
                int mg2 = mg + 8;
                int i = mg2 >> 6, j = mg2 & 63;
                float* p = out + (((size_t)bi * 64 + i) * 64 + j) * 2048 + rem;
                *(float2*)p = make_float2(acc[am][bn][2], acc[am][bn][3]);
            }
        }
    }
}

// ======================= launch ============================================
#define MLP_SMEM (2 * 256 * WST * 4 + 2 * 4 * 256 * 4)

extern "C" void kernel_launch(void* const* d_in, const int* in_sizes, int n_in,
                              void* d_out, int out_size)
{
    const float* x1  = (const float*)d_in[0];
    const float* x2  = (const float*)d_in[1];
    const float* x3  = (const float*)d_in[2];
    const float* x4  = (const float*)d_in[3];
    const float* f   = (const float*)d_in[4];
    const float* Bm  = (const float*)d_in[5];
    const float* tW0 = (const float*)d_in[6];
    const float* tb0 = (const float*)d_in[7];
    const float* tW1 = (const float*)d_in[8];
    const float* tb1 = (const float*)d_in[9];
    const float* tW2 = (const float*)d_in[10];
    const float* tb2 = (const float*)d_in[11];
    const float* tW3 = (const float*)d_in[12];
    const float* tb3 = (const float*)d_in[13];
    const float* bW0 = (const float*)d_in[14];
    const float* bb0 = (const float*)d_in[15];
    const float* bW1 = (const float*)d_in[16];
    const float* bb1 = (const float*)d_in[17];
    const float* bW2 = (const float*)d_in[18];
    const float* bb2 = (const float*)d_in[19];
    const float* bW3 = (const float*)d_in[20];
    const float* bb3 = (const float*)d_in[21];

    cudaFuncSetAttribute(mlp_kernel,
                         cudaFuncAttributeMaxDynamicSharedMemorySize, MLP_SMEM);
    mlp_kernel<<<58, 256, MLP_SMEM>>>(x1, x2, x3, x4, f, Bm,
                                      tW0, tb0, tW1, tb1, tW2, tb2, tW3, tb3,
                                      bW0, bb0, bW1, bb1, bW2, bb2, bW3, bb3);

    pack_kernel<<<1280, 256>>>();

    cudaFuncSetAttribute(gemm_kernel,
                         cudaFuncAttributeMaxDynamicSharedMemorySize, 65536);
    dim3 grid(128, 32);
    gemm_kernel<<<grid, 256, 65536>>>((float*)d_out);
}